// round 1
// baseline (speedup 1.0000x reference)
#include <cuda_runtime.h>
#include <math.h>

#define N_TOTAL 100000
#define NP_TYPE 50000
#define NP_G    50000
#define E_G     500000
#define NH      4
#define HD      64
#define HID     64
#define D       256
#define OUT_DIM 64
#define T_TGT   20000

// ------------------------- scratch (static device globals) -------------------
__device__ float  g_transformed[N_TOTAL * HID];   // 25.6 MB
__device__ float  g_z[NP_G * D];                  // 51.2 MB (reused per graph)
__device__ float  g_el[NP_G * NH];
__device__ float  g_er[NP_G * NH];
__device__ int    g_deg[NP_G];
__device__ int    g_offs[NP_G + 1];
__device__ int    g_cur[NP_G];
__device__ int    g_csr_src[E_G];
__device__ float4 g_csr_ex[E_G];                  // 8 MB
__device__ float  g_gout[NP_G * D];               // 51.2 MB (reused per graph)
__device__ float  g_meta[2 * T_TGT * D];          // 41 MB  (reused per branch)
__device__ float  g_wsum[4];

// ------------------------------ tiny kernels --------------------------------
__global__ void k_zero_wsum() {
    if (threadIdx.x < 4) g_wsum[threadIdx.x] = 0.f;
}

__global__ void k_zero_deg() {
    int i = blockIdx.x * blockDim.x + threadIdx.x;
    if (i < NP_G) g_deg[i] = 0;
}

// --------------------------- fc: type-wise linear ---------------------------
// transformed[type_idx[t][j]] = features_t[j] @ fc_W[t]^T + fc_b[t]
// 16 rows/block, 256 threads (o = tid&63 output col, g = tid>>6 row group of 4)
__global__ __launch_bounds__(256) void k_fc(
    const float* __restrict__ f0, const float* __restrict__ f1,
    const float* __restrict__ fcW, const float* __restrict__ fcb,
    const int* __restrict__ type_idx)
{
    const int ROWS = 16;
    __shared__ float ft[D][ROWS];     // 16 KB (transposed features)
    __shared__ float wt[64][HID];     // 16 KB (W chunk, transposed: wt[k][o])

    int bx = blockIdx.x;
    int t = (bx >= (NP_TYPE / ROWS)) ? 1 : 0;
    int base = (bx - t * (NP_TYPE / ROWS)) * ROWS;
    const float* feat = t ? f1 : f0;
    const float* W = fcW + (size_t)t * HID * D;    // W[o][k], row-major
    int tid = threadIdx.x;
    int o = tid & 63, g = tid >> 6;

    // load ft: 16 rows x 256 cols
    {
        int r = tid >> 4;          // 0..15
        int kq = tid & 15;         // float4 stride
        const float4* src = (const float4*)(feat + (size_t)(base + r) * D);
#pragma unroll
        for (int c = 0; c < 4; c++) {
            float4 v = src[kq + c * 16];
            int k = (kq + c * 16) * 4;
            ft[k + 0][r] = v.x; ft[k + 1][r] = v.y; ft[k + 2][r] = v.z; ft[k + 3][r] = v.w;
        }
    }

    float acc[4] = {0.f, 0.f, 0.f, 0.f};
    for (int ch = 0; ch < 4; ch++) {
        __syncthreads();
        // load W chunk k in [ch*64, ch*64+64): wt[k][oo] = W[oo][ch*64+k]
        {
            int oo = tid >> 2;
            int k4 = tid & 3;
            const float4* wsrc = (const float4*)(W + (size_t)oo * D + ch * 64);
#pragma unroll
            for (int c = 0; c < 4; c++) {
                float4 v = wsrc[k4 + c * 4];
                int k = (k4 + c * 4) * 4;
                wt[k + 0][oo] = v.x; wt[k + 1][oo] = v.y; wt[k + 2][oo] = v.z; wt[k + 3][oo] = v.w;
            }
        }
        __syncthreads();
#pragma unroll
        for (int k = 0; k < 64; k++) {
            float w = wt[k][o];
            int kk = ch * 64 + k;
            float4 f = *(const float4*)&ft[kk][g * 4];
            acc[0] += f.x * w; acc[1] += f.y * w; acc[2] += f.z * w; acc[3] += f.w * w;
        }
    }
    float b = fcb[t * HID + o];
#pragma unroll
    for (int c = 0; c < 4; c++) {
        int r = g * 4 + c;
        int dst = type_idx[t * NP_TYPE + base + r];
        g_transformed[(size_t)dst * HID + o] = acc[c] + b;
    }
}

// ------------------- gat z = gather(transformed) @ gat_W --------------------
// 32 rows/block, 256 threads, thread o owns output col o for all 32 rows
__global__ __launch_bounds__(256) void k_gatz(
    const int* __restrict__ node_idx, const float* __restrict__ gatW)
{
    const int ROWS = 32;
    __shared__ float ft[HID][ROWS];   // 8 KB
    __shared__ float wt[32][D];       // 32 KB (W chunk, W[k][o] is already k-major)

    int base = blockIdx.x * ROWS;
    int tid = threadIdx.x;
    int o = tid;

    // load gathered features: 32 rows x 64
    {
        int r = tid >> 3;
        int kq = tid & 7;
        int nb = base + r;
        if (nb < NP_G) {
            int node = __ldg(&node_idx[nb]);
            const float4* src = (const float4*)(g_transformed + (size_t)node * HID);
#pragma unroll
            for (int c = 0; c < 2; c++) {
                float4 v = src[kq + c * 8];
                int k = (kq + c * 8) * 4;
                ft[k + 0][r] = v.x; ft[k + 1][r] = v.y; ft[k + 2][r] = v.z; ft[k + 3][r] = v.w;
            }
        } else {
#pragma unroll
            for (int c = 0; c < 2; c++) {
                int k = (kq + c * 8) * 4;
                ft[k + 0][r] = 0.f; ft[k + 1][r] = 0.f; ft[k + 2][r] = 0.f; ft[k + 3][r] = 0.f;
            }
        }
    }

    float acc[ROWS];
#pragma unroll
    for (int r = 0; r < ROWS; r++) acc[r] = 0.f;

    for (int ch = 0; ch < 2; ch++) {
        __syncthreads();
        {
            const float4* wsrc = (const float4*)(gatW + (size_t)ch * 32 * D);
            float4* wdst = (float4*)&wt[0][0];
#pragma unroll
            for (int c = 0; c < 8; c++)
                wdst[tid + c * 256] = wsrc[tid + c * 256];
        }
        __syncthreads();
#pragma unroll 8
        for (int k = 0; k < 32; k++) {
            float w = wt[k][o];
            int kk = ch * 32 + k;
#pragma unroll
            for (int rq = 0; rq < 8; rq++) {
                float4 f = *(const float4*)&ft[kk][rq * 4];
                acc[rq * 4 + 0] += f.x * w;
                acc[rq * 4 + 1] += f.y * w;
                acc[rq * 4 + 2] += f.z * w;
                acc[rq * 4 + 3] += f.w * w;
            }
        }
    }
#pragma unroll
    for (int r = 0; r < ROWS; r++) {
        int nb = base + r;
        if (nb < NP_G) g_z[(size_t)nb * D + o] = acc[r];
    }
}

// --------------------- el/er: per-node per-head attn dots -------------------
__global__ __launch_bounds__(256) void k_elr(
    const float* __restrict__ al, const float* __restrict__ ar)
{
    int gw = (blockIdx.x * blockDim.x + threadIdx.x) >> 5;
    if (gw >= NP_G) return;
    int lane = threadIdx.x & 31;
    int h = lane >> 3;
    const float4* zp = (const float4*)(g_z + (size_t)gw * D) + lane * 2;
    float4 z0 = __ldg(zp), z1 = __ldg(zp + 1);
    const float4* alp = (const float4*)al + lane * 2;
    const float4* arp = (const float4*)ar + lane * 2;
    float4 a0 = __ldg(alp), a1 = __ldg(alp + 1);
    float4 r0 = __ldg(arp), r1 = __ldg(arp + 1);
    float el = z0.x * a0.x + z0.y * a0.y + z0.z * a0.z + z0.w * a0.w
             + z1.x * a1.x + z1.y * a1.y + z1.z * a1.z + z1.w * a1.w;
    float er = z0.x * r0.x + z0.y * r0.y + z0.z * r0.z + z0.w * r0.w
             + z1.x * r1.x + z1.y * r1.y + z1.z * r1.z + z1.w * r1.w;
#pragma unroll
    for (int off = 4; off; off >>= 1) {
        el += __shfl_down_sync(0xffffffffu, el, off, 8);
        er += __shfl_down_sync(0xffffffffu, er, off, 8);
    }
    if ((lane & 7) == 0) {
        g_el[gw * NH + h] = el;
        g_er[gw * NH + h] = er;
    }
}

// ------------------------------- CSR build ----------------------------------
__global__ void k_count(const int* __restrict__ dst) {
    int e = blockIdx.x * blockDim.x + threadIdx.x;
    if (e < E_G) atomicAdd(&g_deg[__ldg(&dst[e])], 1);
}

__global__ __launch_bounds__(1024) void k_scan() {
    __shared__ int tmp[1024];
    __shared__ int carry_s;
    int tid = threadIdx.x;
    if (tid == 0) carry_s = 0;
    __syncthreads();
    for (int base = 0; base < NP_G; base += 1024) {
        int i = base + tid;
        int v = (i < NP_G) ? g_deg[i] : 0;
        int val = v;
        tmp[tid] = val;
        __syncthreads();
#pragma unroll
        for (int off = 1; off < 1024; off <<= 1) {
            int add = (tid >= off) ? tmp[tid - off] : 0;
            __syncthreads();
            val += add;
            tmp[tid] = val;
            __syncthreads();
        }
        int carry = carry_s;
        int excl = carry + val - v;
        if (i < NP_G) { g_offs[i] = excl; g_cur[i] = excl; }
        __syncthreads();
        if (tid == 1023) carry_s = carry + val;
        __syncthreads();
    }
    if (tid == 0) g_offs[NP_G] = carry_s;
}

// per-edge: compute exp(leaky(el[src]+er[dst])) per head, scatter into CSR slot
__global__ void k_fill(const int* __restrict__ src, const int* __restrict__ dst) {
    int e = blockIdx.x * blockDim.x + threadIdx.x;
    if (e >= E_G) return;
    int s = __ldg(&src[e]);
    int d = __ldg(&dst[e]);
    float4 elv = *(const float4*)(g_el + (size_t)s * NH);
    float4 erv = *(const float4*)(g_er + (size_t)d * NH);
    float e0 = elv.x + erv.x, e1 = elv.y + erv.y;
    float e2 = elv.z + erv.z, e3 = elv.w + erv.w;
    e0 = e0 > 0.f ? e0 : 0.2f * e0;
    e1 = e1 > 0.f ? e1 : 0.2f * e1;
    e2 = e2 > 0.f ? e2 : 0.2f * e2;
    e3 = e3 > 0.f ? e3 : 0.2f * e3;
    float4 ex = make_float4(expf(e0), expf(e1), expf(e2), expf(e3));
    int pos = atomicAdd(&g_cur[d], 1);
    g_csr_src[pos] = s;
    g_csr_ex[pos] = ex;
}

// --------------- aggregate: warp per dst node, fused softmax ----------------
__global__ __launch_bounds__(256) void k_aggregate() {
    int n = (blockIdx.x * blockDim.x + threadIdx.x) >> 5;
    if (n >= NP_G) return;
    int lane = threadIdx.x & 31;
    int hsel = lane >> 3;
    int beg = g_offs[n], end = g_offs[n + 1];

    float4 a0 = {0.f, 0.f, 0.f, 0.f}, a1 = {0.f, 0.f, 0.f, 0.f};
    float den = 0.f;

    int s_next = 0;
    float4 ex_next = {0.f, 0.f, 0.f, 0.f};
    if (beg < end) {
        s_next = __ldg(&g_csr_src[beg]);
        ex_next = __ldg(&g_csr_ex[beg]);
    }
    for (int i = beg; i < end; i++) {
        int s = s_next;
        float4 ex4 = ex_next;
        if (i + 1 < end) {                 // software prefetch of index+weights
            s_next = __ldg(&g_csr_src[i + 1]);
            ex_next = __ldg(&g_csr_ex[i + 1]);
        }
        float exh = (hsel == 0) ? ex4.x : (hsel == 1) ? ex4.y : (hsel == 2) ? ex4.z : ex4.w;
        const float4* zp = (const float4*)(g_z + (size_t)s * D) + lane * 2;
        float4 z0 = __ldg(zp), z1 = __ldg(zp + 1);
        a0.x += exh * z0.x; a0.y += exh * z0.y; a0.z += exh * z0.z; a0.w += exh * z0.w;
        a1.x += exh * z1.x; a1.y += exh * z1.y; a1.z += exh * z1.z; a1.w += exh * z1.w;
        den += exh;
    }
    float inv = 1.f / (den + 1e-9f);
    float v[8] = {a0.x * inv, a0.y * inv, a0.z * inv, a0.w * inv,
                  a1.x * inv, a1.y * inv, a1.z * inv, a1.w * inv};
#pragma unroll
    for (int j = 0; j < 8; j++) v[j] = v[j] > 0.f ? v[j] : expm1f(v[j]);
    float* op = g_gout + (size_t)n * D + lane * 8;
    *(float4*)op = make_float4(v[0], v[1], v[2], v[3]);
    *((float4*)op + 1) = make_float4(v[4], v[5], v[6], v[7]);
}

// ---------------------- gather target rows into meta ------------------------
__global__ void k_gather(const int* __restrict__ tgt, int m) {
    int t = blockIdx.x, c = threadIdx.x;
    int node = __ldg(&tgt[t]);
    g_meta[((size_t)m * T_TGT + t) * D + c] = __ldg(&g_gout[(size_t)node * D + c]);
}

// ------------- semantic attention: wsum[m] += tanh(zs@W+b)@q ----------------
// rows flat over (m,t): 40000 rows, 32/block (blocks never straddle m)
__global__ __launch_bounds__(256) void k_sem(
    const float* __restrict__ semW, const float* __restrict__ semb,
    const float* __restrict__ semq, int b)
{
    const int ROWS = 32;
    __shared__ float ft[32][ROWS];    // 4 KB per k-chunk
    __shared__ float wt[32][D];       // 32 KB
    __shared__ float red[8];

    int base = blockIdx.x * ROWS;
    int m = base / T_TGT;
    int tid = threadIdx.x;
    int o = tid;

    float acc[ROWS];
#pragma unroll
    for (int r = 0; r < ROWS; r++) acc[r] = 0.f;

    for (int ch = 0; ch < 8; ch++) {
        __syncthreads();
        {   // ft chunk: 32 rows x 32 k
            int r = tid >> 3;
            int kq = tid & 7;
            const float4* srcp = (const float4*)(g_meta + (size_t)(base + r) * D + ch * 32);
            float4 v = __ldg(srcp + kq);
            int k = kq * 4;
            ft[k + 0][r] = v.x; ft[k + 1][r] = v.y; ft[k + 2][r] = v.z; ft[k + 3][r] = v.w;
        }
        {   // W chunk: semW[k][o], k in [ch*32, ..)
            const float4* wsrc = (const float4*)(semW + (size_t)ch * 32 * D);
            float4* wdst = (float4*)&wt[0][0];
#pragma unroll
            for (int c = 0; c < 8; c++)
                wdst[tid + c * 256] = wsrc[tid + c * 256];
        }
        __syncthreads();
#pragma unroll 8
        for (int k = 0; k < 32; k++) {
            float w = wt[k][o];
#pragma unroll
            for (int rq = 0; rq < 8; rq++) {
                float4 f = *(const float4*)&ft[k][rq * 4];
                acc[rq * 4 + 0] += f.x * w;
                acc[rq * 4 + 1] += f.y * w;
                acc[rq * 4 + 2] += f.z * w;
                acc[rq * 4 + 3] += f.w * w;
            }
        }
    }
    float bo = semb[o], qo = semq[o];
    float local = 0.f;
#pragma unroll
    for (int r = 0; r < ROWS; r++) local += tanhf(acc[r] + bo);
    local *= qo;
#pragma unroll
    for (int off = 16; off; off >>= 1)
        local += __shfl_down_sync(0xffffffffu, local, off);
    if ((tid & 31) == 0) red[tid >> 5] = local;
    __syncthreads();
    if (tid < 8) {
        float v = red[tid];
#pragma unroll
        for (int off = 4; off; off >>= 1)
            v += __shfl_down_sync(0xffu, v, off);
        if (tid == 0) atomicAdd(&g_wsum[b * 2 + m], v);
    }
}

// -------------- combine: beta-blend metas, @ fcout_W + bias -----------------
__global__ __launch_bounds__(256) void k_combine(
    const float* __restrict__ fW, const float* __restrict__ fb,
    float* __restrict__ outp, int b)
{
    const int ROWS = 32;
    __shared__ float ft[64][ROWS];     // 8 KB per k-chunk
    __shared__ float wt[64][OUT_DIM];  // 16 KB

    int base = blockIdx.x * ROWS;
    int tid = threadIdx.x;
    int o = tid & 63, g = tid >> 6;

    float w0 = g_wsum[b * 2 + 0] / (float)T_TGT;
    float w1 = g_wsum[b * 2 + 1] / (float)T_TGT;
    float mx = fmaxf(w0, w1);
    float b0 = expf(w0 - mx), b1 = expf(w1 - mx);
    float sm = b0 + b1;
    b0 /= sm; b1 /= sm;

    float acc[8] = {0.f, 0.f, 0.f, 0.f, 0.f, 0.f, 0.f, 0.f};
    for (int ch = 0; ch < 4; ch++) {
        __syncthreads();
        {   // blended ft chunk: 32 rows x 64 k
            int r = tid >> 3;
            int kq = tid & 7;
            const float4* p0 = (const float4*)(g_meta + (size_t)(base + r) * D + ch * 64);
            const float4* p1 = (const float4*)(g_meta + (size_t)(T_TGT + base + r) * D + ch * 64);
#pragma unroll
            for (int c = 0; c < 2; c++) {
                float4 v0 = __ldg(p0 + kq + c * 8);
                float4 v1 = __ldg(p1 + kq + c * 8);
                int k = (kq + c * 8) * 4;
                ft[k + 0][r] = b0 * v0.x + b1 * v1.x;
                ft[k + 1][r] = b0 * v0.y + b1 * v1.y;
                ft[k + 2][r] = b0 * v0.z + b1 * v1.z;
                ft[k + 3][r] = b0 * v0.w + b1 * v1.w;
            }
        }
        {   // fcout_W chunk: fW[k][o], k in [ch*64, ..)
            const float4* wsrc = (const float4*)(fW + (size_t)ch * 64 * OUT_DIM);
            float4* wdst = (float4*)&wt[0][0];
#pragma unroll
            for (int c = 0; c < 4; c++)
                wdst[tid + c * 256] = wsrc[tid + c * 256];
        }
        __syncthreads();
#pragma unroll 8
        for (int k = 0; k < 64; k++) {
            float w = wt[k][o];
            float4 f0 = *(const float4*)&ft[k][g * 8];
            float4 f1 = *(const float4*)&ft[k][g * 8 + 4];
            acc[0] += f0.x * w; acc[1] += f0.y * w; acc[2] += f0.z * w; acc[3] += f0.w * w;
            acc[4] += f1.x * w; acc[5] += f1.y * w; acc[6] += f1.z * w; acc[7] += f1.w * w;
        }
    }
    float bias = fb[o];
#pragma unroll
    for (int c = 0; c < 8; c++) {
        int t = base + g * 8 + c;
        outp[(size_t)t * OUT_DIM + o] = acc[c] + bias;
    }
}

// ------------------------------- launch -------------------------------------
extern "C" void kernel_launch(void* const* d_in, const int* in_sizes, int n_in,
                              void* d_out, int out_size)
{
    const float* features0 = (const float*)d_in[0];
    const float* features1 = (const float*)d_in[1];
    const float* fc_W      = (const float*)d_in[2];
    const float* fc_b      = (const float*)d_in[3];
    const float* gat_W     = (const float*)d_in[4];
    const float* attn_l    = (const float*)d_in[5];
    const float* attn_r    = (const float*)d_in[6];
    const float* sem_W     = (const float*)d_in[7];
    const float* sem_b     = (const float*)d_in[8];
    const float* sem_q     = (const float*)d_in[9];
    const float* fcout_W   = (const float*)d_in[10];
    const float* fcout_b   = (const float*)d_in[11];
    const int*   type_idx  = (const int*)d_in[12];
    const int*   node_idx  = (const int*)d_in[13];
    const int*   edge_src  = (const int*)d_in[14];
    const int*   edge_dst  = (const int*)d_in[15];
    const int*   tgt_idx   = (const int*)d_in[16];
    float* out = (float*)d_out;

    k_zero_wsum<<<1, 32>>>();
    k_fc<<<2 * (NP_TYPE / 16), 256>>>(features0, features1, fc_W, fc_b, type_idx);

    for (int b = 0; b < 2; b++) {
        for (int m = 0; m < 2; m++) {
            int gidx = b * 2 + m;
            k_gatz<<<(NP_G + 31) / 32, 256>>>(node_idx + (size_t)gidx * NP_G,
                                              gat_W + (size_t)gidx * HID * D);
            k_elr<<<NP_G / 8, 256>>>(attn_l + (size_t)gidx * NH * HD,
                                     attn_r + (size_t)gidx * NH * HD);
            k_zero_deg<<<(NP_G + 255) / 256, 256>>>();
            k_count<<<(E_G + 255) / 256, 256>>>(edge_dst + (size_t)gidx * E_G);
            k_scan<<<1, 1024>>>();
            k_fill<<<(E_G + 255) / 256, 256>>>(edge_src + (size_t)gidx * E_G,
                                               edge_dst + (size_t)gidx * E_G);
            k_aggregate<<<NP_G / 8, 256>>>();
            k_gather<<<T_TGT, 256>>>(tgt_idx + (size_t)gidx * T_TGT, m);
        }
        k_sem<<<(2 * T_TGT) / 32, 256>>>(sem_W + (size_t)b * D * D,
                                         sem_b + (size_t)b * D,
                                         sem_q + (size_t)b * D, b);
        k_combine<<<T_TGT / 32, 256>>>(fcout_W + (size_t)b * D * OUT_DIM,
                                       fcout_b + (size_t)b * OUT_DIM,
                                       out + (size_t)b * T_TGT * OUT_DIM, b);
    }
}

// round 3
// speedup vs baseline: 1.6196x; 1.6196x over previous
#include <cuda_runtime.h>
#include <math.h>

#define N_TOTAL 100000
#define NP_TYPE 50000
#define NP_G    50000
#define E_G     500000
#define NH      4
#define HD      64
#define HID     64
#define D       256
#define OUT_DIM 64
#define T_TGT   20000
#define G4      4

// ------------------------- scratch (static device globals) -------------------
__device__ float  g_transformed[N_TOTAL * HID];          // 25.6 MB
__device__ float  g_z[(size_t)G4 * NP_G * D];            // 204.8 MB
__device__ float  g_el[G4 * NP_G * NH];
__device__ float  g_er[G4 * NP_G * NH];
__device__ int    g_deg[G4 * NP_G];
__device__ int    g_offs[G4 * (NP_G + 1)];
__device__ int    g_cur[G4 * NP_G];
__device__ int    g_csr_src[G4 * E_G];
__device__ float4 g_csr_ex[G4 * E_G];                    // 32 MB
__device__ float  g_gout[(size_t)G4 * NP_G * D];         // 204.8 MB
__device__ float  g_meta[(size_t)G4 * T_TGT * D];        // 81.9 MB
__device__ float  g_wsum[4];

__device__ __forceinline__ float fast_tanh(float x) {
    float y;
    asm("tanh.approx.f32 %0, %1;" : "=f"(y) : "f"(x));
    return y;
}

// ------------------------------- init ---------------------------------------
__global__ void k_init() {
    int i = blockIdx.x * blockDim.x + threadIdx.x;
    if (i < G4 * NP_G) g_deg[i] = 0;
    if (i < 4) g_wsum[i] = 0.f;
}

// --------------------------- fc: type-wise linear ---------------------------
// block: 128 rows x 64 cols; 256 threads; thread tile 4 rows x 8 cols
__global__ __launch_bounds__(256) void k_fc(
    const float* __restrict__ f0, const float* __restrict__ f1,
    const float* __restrict__ fcW, const float* __restrict__ fcb,
    const int* __restrict__ type_idx)
{
    __shared__ float ft[64][128];   // 32 KB
    __shared__ float wt[64][64];    // 16 KB

    int t = blockIdx.y;
    int base = blockIdx.x * 128;
    const float* feat = t ? f1 : f0;
    const float* W = fcW + (size_t)t * HID * D;          // W[o][k]
    int tid = threadIdx.x;
    int rg = tid & 31, cg = tid >> 5;

    float acc[4][8];
#pragma unroll
    for (int a = 0; a < 4; a++)
#pragma unroll
        for (int j = 0; j < 8; j++) acc[a][j] = 0.f;

    for (int ch = 0; ch < 4; ch++) {
        __syncthreads();
        {   // ft[k][r] transpose-load: 128 rows x 64 k
            int r = tid & 127, qb = tid >> 7;
            int row = base + r;
            bool val = row < NP_TYPE;
            const float4* fp = (const float4*)(feat + (size_t)row * D) + ch * 16;
#pragma unroll
            for (int i = 0; i < 8; i++) {
                int q = qb + i * 2;
                float4 v = val ? __ldg(fp + q) : make_float4(0.f, 0.f, 0.f, 0.f);
                ft[q * 4 + 0][r] = v.x; ft[q * 4 + 1][r] = v.y;
                ft[q * 4 + 2][r] = v.z; ft[q * 4 + 3][r] = v.w;
            }
        }
        {   // wt[k][o] transpose-load from W[o][k]
            int o = tid & 63, qb = tid >> 6;
            const float4* wp = (const float4*)(W + (size_t)o * D) + ch * 16;
#pragma unroll
            for (int i = 0; i < 4; i++) {
                int q = qb + i * 4;
                float4 v = __ldg(wp + q);
                wt[q * 4 + 0][o] = v.x; wt[q * 4 + 1][o] = v.y;
                wt[q * 4 + 2][o] = v.z; wt[q * 4 + 3][o] = v.w;
            }
        }
        __syncthreads();
#pragma unroll 16
        for (int k = 0; k < 64; k++) {
            float4 fv = *(const float4*)&ft[k][rg * 4];
            float4 w0 = *(const float4*)&wt[k][cg * 8];
            float4 w1 = *(const float4*)&wt[k][cg * 8 + 4];
            float fr[4] = {fv.x, fv.y, fv.z, fv.w};
            float wc[8] = {w0.x, w0.y, w0.z, w0.w, w1.x, w1.y, w1.z, w1.w};
#pragma unroll
            for (int a = 0; a < 4; a++)
#pragma unroll
                for (int j = 0; j < 8; j++) acc[a][j] += fr[a] * wc[j];
        }
    }
    float bo[8];
#pragma unroll
    for (int j = 0; j < 8; j++) bo[j] = __ldg(&fcb[t * HID + cg * 8 + j]);
    const int* ti = type_idx + t * NP_TYPE;
#pragma unroll
    for (int a = 0; a < 4; a++) {
        int row = base + rg * 4 + a;
        if (row < NP_TYPE) {
            int dst = __ldg(&ti[row]);
            float* op = g_transformed + (size_t)dst * HID + cg * 8;
            *(float4*)op = make_float4(acc[a][0] + bo[0], acc[a][1] + bo[1],
                                       acc[a][2] + bo[2], acc[a][3] + bo[3]);
            *((float4*)op + 1) = make_float4(acc[a][4] + bo[4], acc[a][5] + bo[5],
                                             acc[a][6] + bo[6], acc[a][7] + bo[7]);
        }
    }
}

// ------------- gatz (+fused el/er): z = gather(transformed) @ gat_W ---------
// block: 64 rows x 256 cols; 256 threads; thread tile 8 rows x 8 cols
__global__ __launch_bounds__(256) void k_gatz(
    const int* __restrict__ node_idx, const float* __restrict__ gatW,
    const float* __restrict__ attn_l, const float* __restrict__ attn_r)
{
    __shared__ float ft[32][64];    // 8 KB
    __shared__ float wt[32][256];   // 32 KB
    __shared__ int   nd[64];
    __shared__ float al_s[256], ar_s[256];

    int g = blockIdx.y;
    int base = blockIdx.x * 64;
    int tid = threadIdx.x;
    int rg = tid >> 5, cg = tid & 31;   // warp-uniform rg, lane = cg

    if (tid < 64) {
        int rr = base + tid;
        nd[tid] = (rr < NP_G) ? __ldg(&node_idx[(size_t)g * NP_G + rr]) : -1;
    } else if (tid < 128) {
        ((float4*)al_s)[tid - 64] = __ldg((const float4*)(attn_l + (size_t)g * D) + tid - 64);
    } else if (tid < 192) {
        ((float4*)ar_s)[tid - 128] = __ldg((const float4*)(attn_r + (size_t)g * D) + tid - 128);
    }

    float acc[8][8];
#pragma unroll
    for (int a = 0; a < 8; a++)
#pragma unroll
        for (int j = 0; j < 8; j++) acc[a][j] = 0.f;

    for (int ch = 0; ch < 2; ch++) {
        __syncthreads();
        {   // ft[k][r]: 64 rows x 32 k (gathered)
            int r = tid & 63, qb = tid >> 6;
            int node = nd[r];
#pragma unroll
            for (int i = 0; i < 2; i++) {
                int q = qb + i * 4;
                float4 v = (node >= 0)
                    ? __ldg((const float4*)(g_transformed + (size_t)node * HID) + ch * 8 + q)
                    : make_float4(0.f, 0.f, 0.f, 0.f);
                ft[q * 4 + 0][r] = v.x; ft[q * 4 + 1][r] = v.y;
                ft[q * 4 + 2][r] = v.z; ft[q * 4 + 3][r] = v.w;
            }
        }
        {   // wt direct copy (gat_W is k-major: W[k][o])
            const float4* wp = (const float4*)(gatW + (size_t)g * HID * D + (size_t)ch * 32 * D);
            float4* wd = (float4*)&wt[0][0];
#pragma unroll
            for (int i = 0; i < 8; i++)
                wd[tid + i * 256] = __ldg(wp + tid + i * 256);
        }
        __syncthreads();
#pragma unroll 8
        for (int k = 0; k < 32; k++) {
            float4 f0 = *(const float4*)&ft[k][rg * 8];
            float4 f1 = *(const float4*)&ft[k][rg * 8 + 4];
            float4 w0 = *(const float4*)&wt[k][cg * 8];
            float4 w1 = *(const float4*)&wt[k][cg * 8 + 4];
            float fr[8] = {f0.x, f0.y, f0.z, f0.w, f1.x, f1.y, f1.z, f1.w};
            float wc[8] = {w0.x, w0.y, w0.z, w0.w, w1.x, w1.y, w1.z, w1.w};
#pragma unroll
            for (int a = 0; a < 8; a++)
#pragma unroll
                for (int j = 0; j < 8; j++) acc[a][j] += fr[a] * wc[j];
        }
    }

    // stores + fused el/er (head = cg>>3, cols cg*8..cg*8+7 all in one head)
#pragma unroll
    for (int a = 0; a < 8; a++) {
        int row = base + rg * 8 + a;
        bool valid = row < NP_G;
        if (valid) {
            float* zp = g_z + ((size_t)g * NP_G + row) * D + cg * 8;
            *(float4*)zp = make_float4(acc[a][0], acc[a][1], acc[a][2], acc[a][3]);
            *((float4*)zp + 1) = make_float4(acc[a][4], acc[a][5], acc[a][6], acc[a][7]);
        }
        float pl = 0.f, pr = 0.f;
#pragma unroll
        for (int j = 0; j < 8; j++) {
            float zv = acc[a][j];
            pl += zv * al_s[cg * 8 + j];
            pr += zv * ar_s[cg * 8 + j];
        }
#pragma unroll
        for (int off = 4; off; off >>= 1) {
            pl += __shfl_down_sync(0xffffffffu, pl, off, 8);
            pr += __shfl_down_sync(0xffffffffu, pr, off, 8);
        }
        if ((cg & 7) == 0 && valid) {
            int h = cg >> 3;
            g_el[((size_t)g * NP_G + row) * NH + h] = pl;
            g_er[((size_t)g * NP_G + row) * NH + h] = pr;
        }
    }
}

// ------------------------------- CSR build ----------------------------------
__global__ void k_count(const int* __restrict__ dst) {
    int e = blockIdx.x * blockDim.x + threadIdx.x;
    if (e < G4 * E_G) {
        int g = e / E_G;
        atomicAdd(&g_deg[g * NP_G + __ldg(&dst[e])], 1);
    }
}

// one block per graph; warp-shuffle two-pass scan
__global__ __launch_bounds__(1024) void k_scan() {
    __shared__ int ws[32];
    int g = blockIdx.x;
    int tid = threadIdx.x;
    int lane = tid & 31, wid = tid >> 5;
    const int CH = (NP_G + 1023) / 1024;   // 49
    int lo = tid * CH;
    int hi = min(lo + CH, NP_G);
    const int* deg = g_deg + g * NP_G;
    int s = 0;
    for (int i = lo; i < hi; i++) s += deg[i];
    int v = s;
#pragma unroll
    for (int off = 1; off < 32; off <<= 1) {
        int n = __shfl_up_sync(0xffffffffu, v, off);
        if (lane >= off) v += n;
    }
    if (lane == 31) ws[wid] = v;
    __syncthreads();
    if (wid == 0) {
        int w = ws[lane];
#pragma unroll
        for (int off = 1; off < 32; off <<= 1) {
            int n = __shfl_up_sync(0xffffffffu, w, off);
            if (lane >= off) w += n;
        }
        ws[lane] = w;
    }
    __syncthreads();
    int excl = v - s + (wid ? ws[wid - 1] : 0);
    int* offs = g_offs + g * (NP_G + 1);
    int* cur = g_cur + g * NP_G;
    int run = excl;
    for (int i = lo; i < hi; i++) {
        offs[i] = run;
        cur[i] = run;
        run += deg[i];
    }
    if (tid == 0) offs[NP_G] = E_G;
}

__global__ void k_fill(const int* __restrict__ src, const int* __restrict__ dst) {
    int e = blockIdx.x * blockDim.x + threadIdx.x;
    if (e >= G4 * E_G) return;
    int g = e / E_G;
    int gn = g * NP_G;
    int s = __ldg(&src[e]);
    int d = __ldg(&dst[e]);
    float4 elv = __ldg((const float4*)g_el + gn + s);
    float4 erv = __ldg((const float4*)g_er + gn + d);
    float e0 = elv.x + erv.x, e1 = elv.y + erv.y;
    float e2 = elv.z + erv.z, e3 = elv.w + erv.w;
    e0 = e0 > 0.f ? e0 : 0.2f * e0;
    e1 = e1 > 0.f ? e1 : 0.2f * e1;
    e2 = e2 > 0.f ? e2 : 0.2f * e2;
    e3 = e3 > 0.f ? e3 : 0.2f * e3;
    float4 ex = make_float4(__expf(e0), __expf(e1), __expf(e2), __expf(e3));
    int pos = atomicAdd(&g_cur[gn + d], 1);
    g_csr_src[(size_t)g * E_G + pos] = s;
    g_csr_ex[(size_t)g * E_G + pos] = ex;
}

// --------------- aggregate: warp per dst node, fused softmax ----------------
__global__ __launch_bounds__(256) void k_aggregate() {
    int n = (blockIdx.x * blockDim.x + threadIdx.x) >> 5;
    if (n >= G4 * NP_G) return;
    int g = n / NP_G;
    int nl = n - g * NP_G;
    int lane = threadIdx.x & 31;
    int hsel = lane >> 3;
    int beg = g_offs[g * (NP_G + 1) + nl];
    int end = g_offs[g * (NP_G + 1) + nl + 1];
    const int* cs = g_csr_src + (size_t)g * E_G;
    const float4* ce = g_csr_ex + (size_t)g * E_G;
    const float* zb = g_z + (size_t)g * NP_G * D;

    float4 a0 = {0.f, 0.f, 0.f, 0.f}, a1 = {0.f, 0.f, 0.f, 0.f};
    float den = 0.f;

    int i = beg;
    for (; i + 2 <= end; i += 2) {
        int s0 = __ldg(cs + i), s1 = __ldg(cs + i + 1);
        float4 e0 = __ldg(ce + i), e1 = __ldg(ce + i + 1);
        const float4* z0p = (const float4*)(zb + (size_t)s0 * D) + lane * 2;
        const float4* z1p = (const float4*)(zb + (size_t)s1 * D) + lane * 2;
        float4 za = __ldg(z0p), zc = __ldg(z0p + 1);
        float4 zbv = __ldg(z1p), zd = __ldg(z1p + 1);
        float x0 = (hsel == 0) ? e0.x : (hsel == 1) ? e0.y : (hsel == 2) ? e0.z : e0.w;
        float x1 = (hsel == 0) ? e1.x : (hsel == 1) ? e1.y : (hsel == 2) ? e1.z : e1.w;
        a0.x += x0 * za.x; a0.y += x0 * za.y; a0.z += x0 * za.z; a0.w += x0 * za.w;
        a1.x += x0 * zc.x; a1.y += x0 * zc.y; a1.z += x0 * zc.z; a1.w += x0 * zc.w;
        a0.x += x1 * zbv.x; a0.y += x1 * zbv.y; a0.z += x1 * zbv.z; a0.w += x1 * zbv.w;
        a1.x += x1 * zd.x; a1.y += x1 * zd.y; a1.z += x1 * zd.z; a1.w += x1 * zd.w;
        den += x0 + x1;
    }
    if (i < end) {
        int s0 = __ldg(cs + i);
        float4 e0 = __ldg(ce + i);
        const float4* z0p = (const float4*)(zb + (size_t)s0 * D) + lane * 2;
        float4 za = __ldg(z0p), zc = __ldg(z0p + 1);
        float x0 = (hsel == 0) ? e0.x : (hsel == 1) ? e0.y : (hsel == 2) ? e0.z : e0.w;
        a0.x += x0 * za.x; a0.y += x0 * za.y; a0.z += x0 * za.z; a0.w += x0 * za.w;
        a1.x += x0 * zc.x; a1.y += x0 * zc.y; a1.z += x0 * zc.z; a1.w += x0 * zc.w;
        den += x0;
    }
    float inv = 1.f / (den + 1e-9f);
    float v[8] = {a0.x * inv, a0.y * inv, a0.z * inv, a0.w * inv,
                  a1.x * inv, a1.y * inv, a1.z * inv, a1.w * inv};
#pragma unroll
    for (int j = 0; j < 8; j++) v[j] = v[j] > 0.f ? v[j] : expm1f(v[j]);
    float* op = g_gout + (size_t)n * D + lane * 8;
    *(float4*)op = make_float4(v[0], v[1], v[2], v[3]);
    *((float4*)op + 1) = make_float4(v[4], v[5], v[6], v[7]);
}

// ---------------------- gather target rows into meta ------------------------
__global__ void k_gather(const int* __restrict__ tgt) {
    int tid = threadIdx.x;
    int t = blockIdx.x * 4 + (tid >> 6);
    int c = tid & 63;
    int g = t / T_TGT;
    int node = __ldg(&tgt[t]);
    ((float4*)g_meta)[(size_t)t * 64 + c] =
        __ldg((const float4*)g_gout + ((size_t)g * NP_G + node) * 64 + c);
}

// ------------- semantic attention: wsum[m] += tanh(zs@W+b)@q ----------------
// 80000 rows flat; block 64 rows x 256 cols; thread tile 8x8
__global__ __launch_bounds__(256) void k_sem(
    const float* __restrict__ semW, const float* __restrict__ semb,
    const float* __restrict__ semq)
{
    __shared__ float ft[32][64];    // 8 KB
    __shared__ float wt[32][256];   // 32 KB
    __shared__ float bo_s[256], qo_s[256];
    __shared__ float rowsum[64];
    __shared__ float bucket[4];

    int base = blockIdx.x * 64;     // 1250 blocks exactly
    int b = base / (2 * T_TGT);
    const float* W = semW + (size_t)b * D * D;
    int tid = threadIdx.x;
    int rg = tid >> 5, cg = tid & 31;

    if (tid < 64)
        ((float4*)bo_s)[tid] = __ldg((const float4*)(semb + b * D) + tid);
    else if (tid < 128)
        ((float4*)qo_s)[tid - 64] = __ldg((const float4*)(semq + b * D) + tid - 64);
    if (tid < 4) bucket[tid] = 0.f;

    float acc[8][8];
#pragma unroll
    for (int a = 0; a < 8; a++)
#pragma unroll
        for (int j = 0; j < 8; j++) acc[a][j] = 0.f;

    for (int ch = 0; ch < 8; ch++) {
        __syncthreads();
        {
            int r = tid & 63, qb = tid >> 6;
            const float4* fp = (const float4*)(g_meta + ((size_t)base + r) * D) + ch * 8;
#pragma unroll
            for (int i = 0; i < 2; i++) {
                int q = qb + i * 4;
                float4 v = __ldg(fp + q);
                ft[q * 4 + 0][r] = v.x; ft[q * 4 + 1][r] = v.y;
                ft[q * 4 + 2][r] = v.z; ft[q * 4 + 3][r] = v.w;
            }
        }
        {   // sem_W is k-major: direct copy
            const float4* wp = (const float4*)(W + (size_t)ch * 32 * D);
            float4* wd = (float4*)&wt[0][0];
#pragma unroll
            for (int i = 0; i < 8; i++)
                wd[tid + i * 256] = __ldg(wp + tid + i * 256);
        }
        __syncthreads();
#pragma unroll 8
        for (int k = 0; k < 32; k++) {
            float4 f0 = *(const float4*)&ft[k][rg * 8];
            float4 f1 = *(const float4*)&ft[k][rg * 8 + 4];
            float4 w0 = *(const float4*)&wt[k][cg * 8];
            float4 w1 = *(const float4*)&wt[k][cg * 8 + 4];
            float fr[8] = {f0.x, f0.y, f0.z, f0.w, f1.x, f1.y, f1.z, f1.w};
            float wc[8] = {w0.x, w0.y, w0.z, w0.w, w1.x, w1.y, w1.z, w1.w};
#pragma unroll
            for (int a = 0; a < 8; a++)
#pragma unroll
                for (int j = 0; j < 8; j++) acc[a][j] += fr[a] * wc[j];
        }
    }

    float part[8];
#pragma unroll
    for (int a = 0; a < 8; a++) {
        float p = 0.f;
#pragma unroll
        for (int j = 0; j < 8; j++) {
            float x = acc[a][j] + bo_s[cg * 8 + j];
            p += fast_tanh(x) * qo_s[cg * 8 + j];
        }
        part[a] = p;
    }
#pragma unroll
    for (int off = 16; off; off >>= 1)
#pragma unroll
        for (int a = 0; a < 8; a++)
            part[a] += __shfl_down_sync(0xffffffffu, part[a], off);
    if (cg == 0)
#pragma unroll
        for (int a = 0; a < 8; a++) rowsum[rg * 8 + a] = part[a];
    __syncthreads();
    if (tid < 64) {
        int row = base + tid;
        atomicAdd(&bucket[row / T_TGT], rowsum[tid]);
    }
    __syncthreads();
    if (tid < 4 && bucket[tid] != 0.f) atomicAdd(&g_wsum[tid], bucket[tid]);
}

// -------------- combine: beta-blend metas, @ fcout_W + bias -----------------
// block: 128 rows x 64 cols; thread tile 4x8
__global__ __launch_bounds__(256) void k_combine(
    const float* __restrict__ fW, const float* __restrict__ fb,
    float* __restrict__ outp)
{
    __shared__ float ft[64][128];   // 32 KB
    __shared__ float wt[64][64];    // 16 KB

    int b = blockIdx.y;
    int base = blockIdx.x * 128;
    int tid = threadIdx.x;
    int rg = tid & 31, cg = tid >> 5;

    float w0 = g_wsum[b * 2 + 0] * (1.f / T_TGT);
    float w1 = g_wsum[b * 2 + 1] * (1.f / T_TGT);
    float mx = fmaxf(w0, w1);
    float b0 = __expf(w0 - mx), b1 = __expf(w1 - mx);
    float sm = b0 + b1;
    b0 /= sm; b1 /= sm;

    const float* m0 = g_meta + ((size_t)(b * 2 + 0) * T_TGT) * D;
    const float* m1 = g_meta + ((size_t)(b * 2 + 1) * T_TGT) * D;
    const float* W = fW + (size_t)b * D * OUT_DIM;

    float acc[4][8];
#pragma unroll
    for (int a = 0; a < 4; a++)
#pragma unroll
        for (int j = 0; j < 8; j++) acc[a][j] = 0.f;

    for (int ch = 0; ch < 4; ch++) {
        __syncthreads();
        {
            int r = tid & 127, qb = tid >> 7;
            int row = base + r;
            bool val = row < T_TGT;
            const float4* p0 = (const float4*)(m0 + (size_t)row * D) + ch * 16;
            const float4* p1 = (const float4*)(m1 + (size_t)row * D) + ch * 16;
#pragma unroll
            for (int i = 0; i < 8; i++) {
                int q = qb + i * 2;
                float4 v0 = val ? __ldg(p0 + q) : make_float4(0.f, 0.f, 0.f, 0.f);
                float4 v1 = val ? __ldg(p1 + q) : make_float4(0.f, 0.f, 0.f, 0.f);
                ft[q * 4 + 0][r] = b0 * v0.x + b1 * v1.x;
                ft[q * 4 + 1][r] = b0 * v0.y + b1 * v1.y;
                ft[q * 4 + 2][r] = b0 * v0.z + b1 * v1.z;
                ft[q * 4 + 3][r] = b0 * v0.w + b1 * v1.w;
            }
        }
        {   // fcout_W is k-major: direct copy
            const float4* wp = (const float4*)(W + (size_t)ch * 64 * OUT_DIM);
            float4* wd = (float4*)&wt[0][0];
#pragma unroll
            for (int i = 0; i < 4; i++)
                wd[tid + i * 256] = __ldg(wp + tid + i * 256);
        }
        __syncthreads();
#pragma unroll 16
        for (int k = 0; k < 64; k++) {
            float4 fv = *(const float4*)&ft[k][rg * 4];
            float4 wv0 = *(const float4*)&wt[k][cg * 8];
            float4 wv1 = *(const float4*)&wt[k][cg * 8 + 4];
            float fr[4] = {fv.x, fv.y, fv.z, fv.w};
            float wc[8] = {wv0.x, wv0.y, wv0.z, wv0.w, wv1.x, wv1.y, wv1.z, wv1.w};
#pragma unroll
            for (int a = 0; a < 4; a++)
#pragma unroll
                for (int j = 0; j < 8; j++) acc[a][j] += fr[a] * wc[j];
        }
    }
    float bo[8];
#pragma unroll
    for (int j = 0; j < 8; j++) bo[j] = __ldg(&fb[b * OUT_DIM + cg * 8 + j]);
#pragma unroll
    for (int a = 0; a < 4; a++) {
        int row = base + rg * 4 + a;
        if (row < T_TGT) {
            float* op = outp + ((size_t)b * T_TGT + row) * OUT_DIM + cg * 8;
            *(float4*)op = make_float4(acc[a][0] + bo[0], acc[a][1] + bo[1],
                                       acc[a][2] + bo[2], acc[a][3] + bo[3]);
            *((float4*)op + 1) = make_float4(acc[a][4] + bo[4], acc[a][5] + bo[5],
                                             acc[a][6] + bo[6], acc[a][7] + bo[7]);
        }
    }
}

// ------------------------------- launch -------------------------------------
extern "C" void kernel_launch(void* const* d_in, const int* in_sizes, int n_in,
                              void* d_out, int out_size)
{
    const float* features0 = (const float*)d_in[0];
    const float* features1 = (const float*)d_in[1];
    const float* fc_W      = (const float*)d_in[2];
    const float* fc_b      = (const float*)d_in[3];
    const float* gat_W     = (const float*)d_in[4];
    const float* attn_l    = (const float*)d_in[5];
    const float* attn_r    = (const float*)d_in[6];
    const float* sem_W     = (const float*)d_in[7];
    const float* sem_b     = (const float*)d_in[8];
    const float* sem_q     = (const float*)d_in[9];
    const float* fcout_W   = (const float*)d_in[10];
    const float* fcout_b   = (const float*)d_in[11];
    const int*   type_idx  = (const int*)d_in[12];
    const int*   node_idx  = (const int*)d_in[13];
    const int*   edge_src  = (const int*)d_in[14];
    const int*   edge_dst  = (const int*)d_in[15];
    const int*   tgt_idx   = (const int*)d_in[16];
    float* out = (float*)d_out;

    k_init<<<(G4 * NP_G + 255) / 256, 256>>>();
    k_fc<<<dim3((NP_TYPE + 127) / 128, 2), 256>>>(features0, features1, fc_W, fc_b, type_idx);
    k_gatz<<<dim3((NP_G + 63) / 64, G4), 256>>>(node_idx, gat_W, attn_l, attn_r);
    k_count<<<(G4 * E_G + 255) / 256, 256>>>(edge_dst);
    k_scan<<<G4, 1024>>>();
    k_fill<<<(G4 * E_G + 255) / 256, 256>>>(edge_src, edge_dst);
    k_aggregate<<<(G4 * NP_G) / 8, 256>>>();
    k_gather<<<(G4 * T_TGT) / 4, 256>>>(tgt_idx);
    k_sem<<<(G4 * T_TGT) / 64, 256>>>(sem_W, sem_b, sem_q);
    k_combine<<<dim3((T_TGT + 127) / 128, 2), 256>>>(fcout_W, fcout_b, out);
}